// round 8
// baseline (speedup 1.0000x reference)
#include <cuda_runtime.h>
#include <math.h>
#include <stdint.h>
#include <cuda_fp16.h>

#define Bn 8192
#define Hn 512
#define NT 32            // one partial per (row, 256-col ntile)

// Static scratch (allocation-free per harness rules)
__device__ __half g_a1[Bn * Hn];        // 8 MB
__device__ __half g_h[Bn * Hn];         // 8 MB
__device__ __half g_W1t[512 * 512];     // 0.5 MB
__device__ __half g_W2t[8192 * 512];    // 8 MB
__device__ float  g_part[Bn * NT];      // 1 MB

// ---------------------------------------------------------------------------
__device__ __forceinline__ uint32_t smem_u32(const void* p) {
    uint32_t a;
    asm("{ .reg .u64 t; cvta.to.shared.u64 t, %1; cvt.u32.u64 %0, t; }" : "=r"(a) : "l"(p));
    return a;
}
__device__ __forceinline__ float tanh_ap(float x) {
    float y;
    asm("tanh.approx.f32 %0, %1;" : "=f"(y) : "f"(x));
    return y;
}
__device__ __forceinline__ void cp_async16(uint32_t dst, const void* src) {
    asm volatile("cp.async.cg.shared.global [%0], [%1], 16;" :: "r"(dst), "l"(src));
}
__device__ __forceinline__ void cp_commit() { asm volatile("cp.async.commit_group;"); }
__device__ __forceinline__ void cp_wait1() { asm volatile("cp.async.wait_group 1;"); }
__device__ __forceinline__ void cp_wait0() { asm volatile("cp.async.wait_group 0;"); }

__device__ __forceinline__ void ldm_x4(uint32_t* r, uint32_t addr) {
    asm volatile("ldmatrix.sync.aligned.m8n8.x4.shared.b16 {%0,%1,%2,%3}, [%4];"
                 : "=r"(r[0]), "=r"(r[1]), "=r"(r[2]), "=r"(r[3]) : "r"(addr));
}
__device__ __forceinline__ void mma_f16(float& c0, float& c1, float& c2, float& c3,
                                        uint32_t a0, uint32_t a1, uint32_t a2, uint32_t a3,
                                        uint32_t b0, uint32_t b1) {
    asm volatile(
        "mma.sync.aligned.m16n8k16.row.col.f32.f16.f16.f32 "
        "{%0,%1,%2,%3}, {%4,%5,%6,%7}, {%8,%9}, {%0,%1,%2,%3};"
        : "+f"(c0), "+f"(c1), "+f"(c2), "+f"(c3)
        : "r"(a0), "r"(a1), "r"(a2), "r"(a3), "r"(b0), "r"(b1));
}

// Stage: A [128 rows][144B pitch] + B [256 rows][144B pitch]
#define ROW_PITCH 144
#define B_OFF     (128 * ROW_PITCH)              // 18432
#define ST_BYTES  (B_OFF + 256 * ROW_PITCH)      // 55296
#define NSTAGE 3
#define NCHUNK 8
// epilogue tile: 128 x 324 floats = 165888 B == 3 stages exactly
#define TIDX(r, c) ((r) * 324 + (c) + (((c) >> 4) << 2))
#define DYN_SMEM (1024 + NSTAGE * ST_BYTES)

extern __shared__ char dynsmem[];

// ---------------------------------------------------------------------------
// Fused: v_out[:, :512] = v_passive ; g_a1 = fp16(v_passive - 0.5)
// ---------------------------------------------------------------------------
__global__ __launch_bounds__(256) void prep(const float* __restrict__ v_in,
                                            float* __restrict__ v_out) {
    int idx = blockIdx.x * 256 + threadIdx.x;     // Bn*64 groups of 8 floats
    int b = idx >> 6, j = idx & 63;
    const float4* s = reinterpret_cast<const float4*>(v_in) + (size_t)b * 256 + j * 2;
    float4 v0 = s[0], v1 = s[1];
    float4* d = reinterpret_cast<float4*>(v_out) + (size_t)b * 256 + j * 2;
    d[0] = v0; d[1] = v1;
    __half2 o[4];
    o[0] = __floats2half2_rn(v0.x - 0.5f, v0.y - 0.5f);
    o[1] = __floats2half2_rn(v0.z - 0.5f, v0.w - 0.5f);
    o[2] = __floats2half2_rn(v1.x - 0.5f, v1.y - 0.5f);
    o[3] = __floats2half2_rn(v1.z - 0.5f, v1.w - 0.5f);
    *reinterpret_cast<float4*>(g_a1 + (size_t)b * 512 + j * 8) = *reinterpret_cast<float4*>(o);
}

// Transpose W [K][N] -> Wt [N][K] in fp16.
__global__ __launch_bounds__(256) void transposeW(const float* __restrict__ W,
                                                  __half* __restrict__ Wt, int N) {
    __shared__ float t[32][33];
    int x = threadIdx.x & 31, y = threadIdx.x >> 5;
    int n0 = blockIdx.x * 32, k0 = blockIdx.y * 32;
#pragma unroll
    for (int i = 0; i < 32; i += 8)
        t[y + i][x] = W[(size_t)(k0 + y + i) * N + n0 + x];
    __syncthreads();
#pragma unroll
    for (int i = 0; i < 32; i += 8)
        Wt[(size_t)(n0 + y + i) * 512 + k0 + x] = __float2half_rn(t[x][y + i]);
}

// ---------------------------------------------------------------------------
// Mainloop: 128x256 tile, K=512 in 8 chunks of 64 halves, 3-stage cp.async,
// ONE barrier per chunk. 16 warps as 4x4 (warp tile 32 rows x 64 cols).
// ---------------------------------------------------------------------------
#define MMA_MAINLOOP(aptr, bptr)                                                        \
    uint32_t raw = smem_u32(dynsmem);                                                   \
    uint32_t dat = (raw + 1023u) & ~1023u;                                              \
    uint32_t delta = dat - raw;                                                         \
    int tid = threadIdx.x;                                                              \
    int w = tid >> 5, lane = tid & 31;                                                  \
    int wr = w >> 2, wc = w & 3;                                                        \
    int rowBase = blockIdx.y * 128, colBase = blockIdx.x * 256;                         \
    const __half* Abase = (aptr) + (size_t)rowBase * 512;                               \
    const __half* Bbase = (bptr) + (size_t)colBase * 512;                               \
    float acc[2][8][4];                                                                 \
    _Pragma("unroll") for (int i = 0; i < 2; i++)                                       \
        _Pragma("unroll") for (int j = 0; j < 8; j++)                                   \
            _Pragma("unroll") for (int q = 0; q < 4; q++) acc[i][j][q] = 0.f;           \
    auto load_chunk = [&](int chunk, int s) {                                           \
        int k0 = chunk * 64;                                                            \
        uint32_t sb = dat + (uint32_t)s * ST_BYTES;                                     \
        _Pragma("unroll") for (int j = 0; j < 6; j++) {                                 \
            int idx = tid + j * 512;                                                    \
            int f4 = idx & 7;                                                           \
            if (idx < 1024) {                                                           \
                int row = idx >> 3;                                                     \
                cp_async16(sb + (uint32_t)(row * ROW_PITCH + f4 * 16),                  \
                           Abase + (size_t)row * 512 + k0 + f4 * 8);                    \
            } else {                                                                    \
                int row = (idx - 1024) >> 3;                                            \
                cp_async16(sb + B_OFF + (uint32_t)(row * ROW_PITCH + f4 * 16),          \
                           Bbase + (size_t)row * 512 + k0 + f4 * 8);                    \
            }                                                                           \
        }                                                                               \
        cp_commit();                                                                    \
    };                                                                                  \
    load_chunk(0, 0);                                                                   \
    load_chunk(1, 1);                                                                   \
    uint32_t aBase16 = (uint32_t)((wr * 32 + (lane & 15)) * ROW_PITCH + (lane >> 4) * 16); \
    uint32_t bBase16 = B_OFF + (uint32_t)((wc * 64 + (lane & 15)) * ROW_PITCH + (lane >> 4) * 16); \
    _Pragma("unroll") for (int i = 0; i < NCHUNK; i++) {                                \
        if (i < NCHUNK - 1) cp_wait1(); else cp_wait0();                                \
        __syncthreads();                                                                \
        uint32_t stg = dat + (uint32_t)(i % NSTAGE) * ST_BYTES;                         \
        _Pragma("unroll") for (int ks = 0; ks < 4; ks++) {                              \
            uint32_t af[2][4], bf[4][4];                                                \
            _Pragma("unroll") for (int mf = 0; mf < 2; mf++)                            \
                ldm_x4(af[mf], stg + aBase16 + (uint32_t)(mf * 16 * ROW_PITCH + ks * 32)); \
            _Pragma("unroll") for (int nfp = 0; nfp < 4; nfp++)                         \
                ldm_x4(bf[nfp], stg + bBase16 + (uint32_t)(nfp * 16 * ROW_PITCH + ks * 32)); \
            _Pragma("unroll") for (int mf = 0; mf < 2; mf++)                            \
                _Pragma("unroll") for (int nfp = 0; nfp < 4; nfp++) {                   \
                    mma_f16(acc[mf][nfp*2][0], acc[mf][nfp*2][1],                       \
                            acc[mf][nfp*2][2], acc[mf][nfp*2][3],                       \
                            af[mf][0], af[mf][1], af[mf][2], af[mf][3],                 \
                            bf[nfp][0], bf[nfp][2]);                                    \
                    mma_f16(acc[mf][nfp*2+1][0], acc[mf][nfp*2+1][1],                   \
                            acc[mf][nfp*2+1][2], acc[mf][nfp*2+1][3],                   \
                            af[mf][0], af[mf][1], af[mf][2], af[mf][3],                 \
                            bf[nfp][1], bf[nfp][3]);                                    \
                }                                                                       \
        }                                                                               \
        if (i + 2 < NCHUNK) load_chunk(i + 2, (i + 2) % NSTAGE);                        \
    }                                                                                   \
    __syncthreads();

// ---------------------------------------------------------------------------
// GEMM1: g_h = fp16( tanh( g_a1 @ W1 + b1 ) ).  Grid (2, 64), 512 thr.
// ---------------------------------------------------------------------------
__global__ __launch_bounds__(512, 1) void gemm1(const float* __restrict__ b1) {
    MMA_MAINLOOP(g_a1, g_W1t)

#pragma unroll
    for (int mf = 0; mf < 2; mf++) {
#pragma unroll
        for (int nf = 0; nf < 8; nf++) {
            int R0 = wr * 32 + mf * 16 + (lane >> 2);
            int C0 = wc * 64 + nf * 8 + 2 * (lane & 3);
            float bias0 = b1[colBase + C0], bias1 = b1[colBase + C0 + 1];
            __half2 lo = __floats2half2_rn(tanh_ap(acc[mf][nf][0] + bias0),
                                           tanh_ap(acc[mf][nf][1] + bias1));
            __half2 hi = __floats2half2_rn(tanh_ap(acc[mf][nf][2] + bias0),
                                           tanh_ap(acc[mf][nf][3] + bias1));
            *reinterpret_cast<__half2*>(g_h + (size_t)(rowBase + R0) * 512 + colBase + C0) = lo;
            *reinterpret_cast<__half2*>(g_h + (size_t)(rowBase + R0 + 8) * 512 + colBase + C0) = hi;
        }
    }
}

// ---------------------------------------------------------------------------
// GEMM2: net = tanh(g_h @ W2 + b2) fused softmax/spline/log.  Grid (32, 64).
// ---------------------------------------------------------------------------
__global__ __launch_bounds__(512, 1) void gemm2(const float* __restrict__ v_in,
                                                const float* __restrict__ b2,
                                                float* __restrict__ v_out) {
    MMA_MAINLOOP(g_h, g_W2t)

    float* tile = (float*)(dynsmem + delta);
#pragma unroll
    for (int mf = 0; mf < 2; mf++) {
#pragma unroll
        for (int nf = 0; nf < 8; nf++) {
            int R0 = wr * 32 + mf * 16 + (lane >> 2);
            int C0 = wc * 64 + nf * 8 + 2 * (lane & 3);
            float bias0 = b2[colBase + C0], bias1 = b2[colBase + C0 + 1];
            tile[TIDX(R0, C0)]         = tanh_ap(acc[mf][nf][0] + bias0);
            tile[TIDX(R0, C0 + 1)]     = tanh_ap(acc[mf][nf][1] + bias1);
            tile[TIDX(R0 + 8, C0)]     = tanh_ap(acc[mf][nf][2] + bias0);
            tile[TIDX(R0 + 8, C0 + 1)] = tanh_ap(acc[mf][nf][3] + bias1);
        }
    }
    __syncthreads();

    // 2048 cells (128 rows x 16 groups) over 512 threads
    float nlp_acc[4];
#pragma unroll
    for (int jj = 0; jj < 4; jj++) {
        int cell = jj * 512 + tid;
        int r = cell >> 4, g = cell & 15;
        int bglob = rowBase + r;
        int hglob = blockIdx.x * 16 + g;

        float n[16];
#pragma unroll
        for (int c4 = 0; c4 < 4; c4++)
            *(float4*)&n[c4 * 4] = *(const float4*)&tile[TIDX(r, g * 16 + c4 * 4)];

        float v = v_in[(size_t)bglob * 1024 + 512 + hglob];
        int kk = (int)ceilf(v * 16.0f) - 1;
        kk = kk < 0 ? 0 : (kk > 15 ? 15 : kk);

        float m = n[0];
#pragma unroll
        for (int c = 1; c < 16; c++) m = fmaxf(m, n[c]);
        float ssum = 0.f, pre = 0.f, ek = 0.f, nk = 0.f;
#pragma unroll
        for (int c = 0; c < 16; c++) {
            float ec = __expf(n[c] - m);
            ssum += ec;
            if (c < kk)  pre += ec;
            if (c == kk) { ek = ec; nk = n[c]; }
        }
        float inv = 1.0f / ssum;
        float p_k  = ek * inv;
        float y_lo = pre * inv;
        float alpha = (v - (float)kk * 0.0625f) * 16.0f;
        v_out[(size_t)bglob * 1024 + 512 + hglob] = y_lo + alpha * p_k;
        nlp_acc[jj] = __logf(ssum) + m - nk;
    }
#pragma unroll
    for (int jj = 0; jj < 4; jj++) {
        float nlp = nlp_acc[jj];
        nlp += __shfl_down_sync(0xffffffffu, nlp, 8, 16);
        nlp += __shfl_down_sync(0xffffffffu, nlp, 4, 16);
        nlp += __shfl_down_sync(0xffffffffu, nlp, 2, 16);
        nlp += __shfl_down_sync(0xffffffffu, nlp, 1, 16);
        int cell = jj * 512 + tid;
        if ((cell & 15) == 0)
            g_part[(size_t)(rowBase + (cell >> 4)) * NT + blockIdx.x] = nlp;
    }
}

// ---------------------------------------------------------------------------
// reduce_log: one warp per row; lane reads one of 32 partials.
// ---------------------------------------------------------------------------
__global__ __launch_bounds__(256) void reduce_log(const float* __restrict__ log_density,
                                                  float* __restrict__ out_log) {
    int row = blockIdx.x * 8 + (threadIdx.x >> 5);
    int lane = threadIdx.x & 31;
    float s = g_part[(size_t)row * NT + lane];
#pragma unroll
    for (int o = 16; o > 0; o >>= 1) s += __shfl_down_sync(0xffffffffu, s, o);
    if (lane == 0) out_log[row] = log_density[row] + s;
}

// ---------------------------------------------------------------------------
extern "C" void kernel_launch(void* const* d_in, const int* in_sizes, int n_in,
                              void* d_out, int out_size) {
    const float* v_in        = (const float*)d_in[0];
    const float* log_density = (const float*)d_in[1];
    const float* W1          = (const float*)d_in[2];
    const float* b1          = (const float*)d_in[3];
    const float* W2          = (const float*)d_in[4];
    const float* b2          = (const float*)d_in[5];
    float* v_out   = (float*)d_out;
    float* log_out = (float*)d_out + (size_t)Bn * 1024;

    cudaFuncSetAttribute(gemm1, cudaFuncAttributeMaxDynamicSharedMemorySize, DYN_SMEM);
    cudaFuncSetAttribute(gemm2, cudaFuncAttributeMaxDynamicSharedMemorySize, DYN_SMEM);

    prep<<<(Bn * 64) / 256, 256>>>(v_in, v_out);
    __half* w1t = nullptr; __half* w2t = nullptr;
    cudaGetSymbolAddress((void**)&w1t, g_W1t);
    cudaGetSymbolAddress((void**)&w2t, g_W2t);
    transposeW<<<dim3(512 / 32, 512 / 32), 256>>>(W1, w1t, 512);
    transposeW<<<dim3(8192 / 32, 512 / 32), 256>>>(W2, w2t, 8192);
    gemm1<<<dim3(2, 64), 512, DYN_SMEM>>>(b1);
    gemm2<<<dim3(32, 64), 512, DYN_SMEM>>>(v_in, b2, v_out);
    reduce_log<<<Bn / 8, 256>>>(log_density, log_out);
}

// round 10
// speedup vs baseline: 1.0408x; 1.0408x over previous
#include <cuda_runtime.h>
#include <math.h>
#include <stdint.h>
#include <cuda_fp16.h>

#define Bn 8192
#define Hn 512
#define NT 32            // one partial per (row, 256-col ntile)
#define ROW_PITCH 144
#define NCHUNK 8
#define NSTAGE 3

// Static scratch (allocation-free per harness rules)
__device__ __half g_a1[Bn * Hn];        // 8 MB
__device__ __half g_h[Bn * Hn];         // 8 MB
__device__ __half g_W1t[512 * 512];     // 0.5 MB
__device__ __half g_W2t[8192 * 512];    // 8 MB
__device__ float  g_part[Bn * NT];      // 1 MB

// ---------------------------------------------------------------------------
__device__ __forceinline__ uint32_t smem_u32(const void* p) {
    uint32_t a;
    asm("{ .reg .u64 t; cvta.to.shared.u64 t, %1; cvt.u32.u64 %0, t; }" : "=r"(a) : "l"(p));
    return a;
}
__device__ __forceinline__ float tanh_ap(float x) {
    float y;
    asm("tanh.approx.f32 %0, %1;" : "=f"(y) : "f"(x));
    return y;
}
__device__ __forceinline__ void cp_async16(uint32_t dst, const void* src) {
    asm volatile("cp.async.cg.shared.global [%0], [%1], 16;" :: "r"(dst), "l"(src));
}
__device__ __forceinline__ void cp_commit() { asm volatile("cp.async.commit_group;"); }
__device__ __forceinline__ void cp_wait1() { asm volatile("cp.async.wait_group 1;"); }
__device__ __forceinline__ void cp_wait0() { asm volatile("cp.async.wait_group 0;"); }

__device__ __forceinline__ void ldm_x4(uint32_t* r, uint32_t addr) {
    asm volatile("ldmatrix.sync.aligned.m8n8.x4.shared.b16 {%0,%1,%2,%3}, [%4];"
                 : "=r"(r[0]), "=r"(r[1]), "=r"(r[2]), "=r"(r[3]) : "r"(addr));
}
// fp16-accumulator MMA: D,C are f16x2 pairs (2 regs)
__device__ __forceinline__ void mma_f16acc(uint32_t& d0, uint32_t& d1,
                                           uint32_t a0, uint32_t a1, uint32_t a2, uint32_t a3,
                                           uint32_t b0, uint32_t b1) {
    asm volatile(
        "mma.sync.aligned.m16n8k16.row.col.f16.f16.f16.f16 "
        "{%0,%1}, {%2,%3,%4,%5}, {%6,%7}, {%0,%1};"
        : "+r"(d0), "+r"(d1)
        : "r"(a0), "r"(a1), "r"(a2), "r"(a3), "r"(b0), "r"(b1));
}

#define B_OFF 18432                                  // 128 * ROW_PITCH
// gemm2 epilogue tile: 128 x 324 floats = 165888 B == 3 stages (BN=256) exactly
#define TIDX(r, c) ((r) * 324 + (c) + (((c) >> 4) << 2))
#define DYN1 (1024 + NSTAGE * (256 * ROW_PITCH))     // 111616
#define DYN2 (1024 + NSTAGE * (384 * ROW_PITCH))     // 166912

extern __shared__ char dynsmem[];

// ---------------------------------------------------------------------------
// Fused: v_out[:, :512] = v_passive ; g_a1 = fp16(v_passive - 0.5)
// ---------------------------------------------------------------------------
__global__ __launch_bounds__(256) void prep(const float* __restrict__ v_in,
                                            float* __restrict__ v_out) {
    int idx = blockIdx.x * 256 + threadIdx.x;
    int b = idx >> 6, j = idx & 63;
    const float4* s = reinterpret_cast<const float4*>(v_in) + (size_t)b * 256 + j * 2;
    float4 v0 = s[0], v1 = s[1];
    float4* d = reinterpret_cast<float4*>(v_out) + (size_t)b * 256 + j * 2;
    d[0] = v0; d[1] = v1;
    __half2 o[4];
    o[0] = __floats2half2_rn(v0.x - 0.5f, v0.y - 0.5f);
    o[1] = __floats2half2_rn(v0.z - 0.5f, v0.w - 0.5f);
    o[2] = __floats2half2_rn(v1.x - 0.5f, v1.y - 0.5f);
    o[3] = __floats2half2_rn(v1.z - 0.5f, v1.w - 0.5f);
    *reinterpret_cast<float4*>(g_a1 + (size_t)b * 512 + j * 8) = *reinterpret_cast<float4*>(o);
}

__global__ __launch_bounds__(256) void transposeW(const float* __restrict__ W,
                                                  __half* __restrict__ Wt, int N) {
    __shared__ float t[32][33];
    int x = threadIdx.x & 31, y = threadIdx.x >> 5;
    int n0 = blockIdx.x * 32, k0 = blockIdx.y * 32;
#pragma unroll
    for (int i = 0; i < 32; i += 8)
        t[y + i][x] = W[(size_t)(k0 + y + i) * N + n0 + x];
    __syncthreads();
#pragma unroll
    for (int i = 0; i < 32; i += 8)
        Wt[(size_t)(n0 + y + i) * 512 + k0 + x] = __float2half_rn(t[x][y + i]);
}

// ---------------------------------------------------------------------------
// Mainloop template: 128 x BN tile, K=512 in 8 chunks of 64 halves, 3-stage
// cp.async, one barrier per chunk. 512 threads, 16 warps as 4x4,
// warp tile 32 x (BN/4). fp16 accumulators (f16x2-packed).
// ---------------------------------------------------------------------------
template<int BN>
__device__ __forceinline__ void run_mainloop(const __half* __restrict__ Abase,
                                             const __half* __restrict__ Bbase,
                                             uint32_t dat,
                                             uint32_t (&acc)[2][BN / 32][2]) {
    constexpr int STB = (128 + BN) * ROW_PITCH;
    constexpr int LDJ = (128 + BN) / 64;      // cp.async per thread per chunk
    int tid = threadIdx.x;
    int w = tid >> 5, lane = tid & 31;
    int wr = w >> 2, wc = w & 3;

#pragma unroll
    for (int i = 0; i < 2; i++)
#pragma unroll
        for (int j = 0; j < BN / 32; j++) { acc[i][j][0] = 0u; acc[i][j][1] = 0u; }

    auto load_chunk = [&](int chunk, int s) {
        int k0 = chunk * 64;
        uint32_t sb = dat + (uint32_t)s * STB;
#pragma unroll
        for (int j = 0; j < LDJ; j++) {
            int idx = tid + j * 512;
            int f4 = idx & 7;
            if (idx < 1024) {
                int row = idx >> 3;
                cp_async16(sb + (uint32_t)(row * ROW_PITCH + f4 * 16),
                           Abase + (size_t)row * 512 + k0 + f4 * 8);
            } else {
                int row = (idx - 1024) >> 3;
                cp_async16(sb + B_OFF + (uint32_t)(row * ROW_PITCH + f4 * 16),
                           Bbase + (size_t)row * 512 + k0 + f4 * 8);
            }
        }
        cp_commit();
    };
    load_chunk(0, 0);
    load_chunk(1, 1);

    uint32_t aOff = (uint32_t)((wr * 32 + (lane & 15)) * ROW_PITCH + (lane >> 4) * 16);
    uint32_t bOff = B_OFF + (uint32_t)((wc * (BN / 4) + (lane & 15)) * ROW_PITCH + (lane >> 4) * 16);

#pragma unroll
    for (int i = 0; i < NCHUNK; i++) {
        if (i < NCHUNK - 1) cp_wait1(); else cp_wait0();
        __syncthreads();
        uint32_t stg = dat + (uint32_t)(i % NSTAGE) * STB;
#pragma unroll
        for (int ks = 0; ks < 4; ks++) {
            uint32_t af[2][4];
#pragma unroll
            for (int mf = 0; mf < 2; mf++)
                ldm_x4(af[mf], stg + aOff + (uint32_t)(mf * 16 * ROW_PITCH + ks * 32));
#pragma unroll
            for (int nfp = 0; nfp < BN / 64; nfp++) {
                uint32_t bf[4];
                ldm_x4(bf, stg + bOff + (uint32_t)(nfp * 16 * ROW_PITCH + ks * 32));
#pragma unroll
                for (int mf = 0; mf < 2; mf++) {
                    mma_f16acc(acc[mf][nfp * 2][0], acc[mf][nfp * 2][1],
                               af[mf][0], af[mf][1], af[mf][2], af[mf][3],
                               bf[0], bf[2]);
                    mma_f16acc(acc[mf][nfp * 2 + 1][0], acc[mf][nfp * 2 + 1][1],
                               af[mf][0], af[mf][1], af[mf][2], af[mf][3],
                               bf[1], bf[3]);
                }
            }
        }
        if (i + 2 < NCHUNK) load_chunk(i + 2, (i + 2) % NSTAGE);
    }
    __syncthreads();
}

// ---------------------------------------------------------------------------
// GEMM1: g_h = fp16( tanh( g_a1 @ W1 + b1 ) ).  BN=128, grid (4, 64), 512 thr.
// ---------------------------------------------------------------------------
__global__ __launch_bounds__(512, 1) void gemm1(const float* __restrict__ b1) {
    uint32_t raw = smem_u32(dynsmem);
    uint32_t dat = (raw + 1023u) & ~1023u;
    int tid = threadIdx.x;
    int w = tid >> 5, lane = tid & 31;
    int wr = w >> 2, wc = w & 3;
    int rowBase = blockIdx.y * 128, colBase = blockIdx.x * 128;

    uint32_t acc[2][4][2];
    run_mainloop<128>(g_a1 + (size_t)rowBase * 512, g_W1t + (size_t)colBase * 512, dat, acc);

#pragma unroll
    for (int mf = 0; mf < 2; mf++) {
#pragma unroll
        for (int nf = 0; nf < 4; nf++) {
            int R0 = wr * 32 + mf * 16 + (lane >> 2);
            int C0 = wc * 32 + nf * 8 + 2 * (lane & 3);
            float bias0 = b1[colBase + C0], bias1 = b1[colBase + C0 + 1];
            float2 lo = __half22float2(*reinterpret_cast<__half2*>(&acc[mf][nf][0]));
            float2 hi = __half22float2(*reinterpret_cast<__half2*>(&acc[mf][nf][1]));
            __half2 l2 = __floats2half2_rn(tanh_ap(lo.x + bias0), tanh_ap(lo.y + bias1));
            __half2 h2 = __floats2half2_rn(tanh_ap(hi.x + bias0), tanh_ap(hi.y + bias1));
            *reinterpret_cast<__half2*>(g_h + (size_t)(rowBase + R0) * 512 + colBase + C0) = l2;
            *reinterpret_cast<__half2*>(g_h + (size_t)(rowBase + R0 + 8) * 512 + colBase + C0) = h2;
        }
    }
}

// ---------------------------------------------------------------------------
// GEMM2: net = tanh(g_h @ W2 + b2) fused softmax/spline/log.
// BN=256, grid (32, 64), 512 thr.
// ---------------------------------------------------------------------------
__global__ __launch_bounds__(512, 1) void gemm2(const float* __restrict__ v_in,
                                                const float* __restrict__ b2,
                                                float* __restrict__ v_out) {
    uint32_t raw = smem_u32(dynsmem);
    uint32_t dat = (raw + 1023u) & ~1023u;
    uint32_t delta = dat - raw;
    int tid = threadIdx.x;
    int w = tid >> 5, lane = tid & 31;
    int wr = w >> 2, wc = w & 3;
    int rowBase = blockIdx.y * 128, colBase = blockIdx.x * 256;

    uint32_t acc[2][8][2];
    run_mainloop<256>(g_h + (size_t)rowBase * 512, g_W2t + (size_t)colBase * 512, dat, acc);

    float* tile = (float*)(dynsmem + delta);
#pragma unroll
    for (int mf = 0; mf < 2; mf++) {
#pragma unroll
        for (int nf = 0; nf < 8; nf++) {
            int R0 = wr * 32 + mf * 16 + (lane >> 2);
            int C0 = wc * 64 + nf * 8 + 2 * (lane & 3);
            float bias0 = b2[colBase + C0], bias1 = b2[colBase + C0 + 1];
            float2 lo = __half22float2(*reinterpret_cast<__half2*>(&acc[mf][nf][0]));
            float2 hi = __half22float2(*reinterpret_cast<__half2*>(&acc[mf][nf][1]));
            tile[TIDX(R0, C0)]         = tanh_ap(lo.x + bias0);
            tile[TIDX(R0, C0 + 1)]     = tanh_ap(lo.y + bias1);
            tile[TIDX(R0 + 8, C0)]     = tanh_ap(hi.x + bias0);
            tile[TIDX(R0 + 8, C0 + 1)] = tanh_ap(hi.y + bias1);
        }
    }
    __syncthreads();

    // 2048 cells (128 rows x 16 groups) over 512 threads
    float nlp_acc[4];
#pragma unroll
    for (int jj = 0; jj < 4; jj++) {
        int cell = jj * 512 + tid;
        int r = cell >> 4, g = cell & 15;
        int bglob = rowBase + r;
        int hglob = blockIdx.x * 16 + g;

        float n[16];
#pragma unroll
        for (int c4 = 0; c4 < 4; c4++)
            *(float4*)&n[c4 * 4] = *(const float4*)&tile[TIDX(r, g * 16 + c4 * 4)];

        float v = v_in[(size_t)bglob * 1024 + 512 + hglob];
        int kk = (int)ceilf(v * 16.0f) - 1;
        kk = kk < 0 ? 0 : (kk > 15 ? 15 : kk);

        float m = n[0];
#pragma unroll
        for (int c = 1; c < 16; c++) m = fmaxf(m, n[c]);
        float ssum = 0.f, pre = 0.f, ek = 0.f, nk = 0.f;
#pragma unroll
        for (int c = 0; c < 16; c++) {
            float ec = __expf(n[c] - m);
            ssum += ec;
            if (c < kk)  pre += ec;
            if (c == kk) { ek = ec; nk = n[c]; }
        }
        float inv = 1.0f / ssum;
        float p_k  = ek * inv;
        float y_lo = pre * inv;
        float alpha = (v - (float)kk * 0.0625f) * 16.0f;
        v_out[(size_t)bglob * 1024 + 512 + hglob] = y_lo + alpha * p_k;
        nlp_acc[jj] = __logf(ssum) + m - nk;
    }
#pragma unroll
    for (int jj = 0; jj < 4; jj++) {
        float nlp = nlp_acc[jj];
        nlp += __shfl_down_sync(0xffffffffu, nlp, 8, 16);
        nlp += __shfl_down_sync(0xffffffffu, nlp, 4, 16);
        nlp += __shfl_down_sync(0xffffffffu, nlp, 2, 16);
        nlp += __shfl_down_sync(0xffffffffu, nlp, 1, 16);
        int cell = jj * 512 + tid;
        if ((cell & 15) == 0)
            g_part[(size_t)(rowBase + (cell >> 4)) * NT + blockIdx.x] = nlp;
    }
}

// ---------------------------------------------------------------------------
__global__ __launch_bounds__(256) void reduce_log(const float* __restrict__ log_density,
                                                  float* __restrict__ out_log) {
    int row = blockIdx.x * 8 + (threadIdx.x >> 5);
    int lane = threadIdx.x & 31;
    float s = g_part[(size_t)row * NT + lane];
#pragma unroll
    for (int o = 16; o > 0; o >>= 1) s += __shfl_down_sync(0xffffffffu, s, o);
    if (lane == 0) out_log[row] = log_density[row] + s;
}

// ---------------------------------------------------------------------------
extern "C" void kernel_launch(void* const* d_in, const int* in_sizes, int n_in,
                              void* d_out, int out_size) {
    const float* v_in        = (const float*)d_in[0];
    const float* log_density = (const float*)d_in[1];
    const float* W1          = (const float*)d_in[2];
    const float* b1          = (const float*)d_in[3];
    const float* W2          = (const float*)d_in[4];
    const float* b2          = (const float*)d_in[5];
    float* v_out   = (float*)d_out;
    float* log_out = (float*)d_out + (size_t)Bn * 1024;

    cudaFuncSetAttribute(gemm1, cudaFuncAttributeMaxDynamicSharedMemorySize, DYN1);
    cudaFuncSetAttribute(gemm2, cudaFuncAttributeMaxDynamicSharedMemorySize, DYN2);

    prep<<<(Bn * 64) / 256, 256>>>(v_in, v_out);
    __half* w1t = nullptr; __half* w2t = nullptr;
    cudaGetSymbolAddress((void**)&w1t, g_W1t);
    cudaGetSymbolAddress((void**)&w2t, g_W2t);
    transposeW<<<dim3(512 / 32, 512 / 32), 256>>>(W1, w1t, 512);
    transposeW<<<dim3(8192 / 32, 512 / 32), 256>>>(W2, w2t, 8192);
    gemm1<<<dim3(4, 64), 512, DYN1>>>(b1);
    gemm2<<<dim3(32, 64), 512, DYN2>>>(v_in, b2, v_out);
    reduce_log<<<Bn / 8, 256>>>(log_density, log_out);
}